// round 11
// baseline (speedup 1.0000x reference)
#include <cuda_runtime.h>

#define NN 50000
#define EE 800000
#define ET (EE + NN)

// ---------------- scratch (device globals; no allocations allowed) ----------
__device__ float g_xl[NN * 128];     // transformed features [N, M]
__device__ float g_h[NN * 128];      // inter-layer activations
__device__ float g_s[NN * 2];        // alpha_src per (node, head)
__device__ float g_d[NN * 2];        // alpha_dst per (node, head)
__device__ int   g_rowptr[NN + 1];   // CSR row pointers (by dst)
__device__ int   g_cnt[NN];          // degree counts / fill cursors
__device__ int   g_src[ET];          // CSR: src node per incoming edge

// ---------------- GEMM: [N,128] @ [128,BN] -> g_xl[N,BN] --------------------
// 128xBNx16 tile, 256 threads, 8x(BN/16) per thread, double-buffered smem.
template <int BN>
__global__ void __launch_bounds__(256) gemm_kernel(const float* __restrict__ A,
                                                   const float* __restrict__ B,
                                                   int src_is_gh) {
    constexpr int BM = 128, BK = 16, TM = 8, TN = BN / 16;
    constexpr int BL = (BK * BN) / (4 * 256);   // B float4 loads per thread
    __shared__ float As[2][BK][BM + 4];
    __shared__ float Bs[2][BK][BN];
    const float* __restrict__ Ab = src_is_gh ? (const float*)g_h : A;
    const int tid = threadIdx.x;
    const int tx = tid & 15, ty = tid >> 4;
    const int row0 = blockIdx.x * BM;

    float acc[TM][TN];
#pragma unroll
    for (int i = 0; i < TM; i++)
#pragma unroll
        for (int j = 0; j < TN; j++) acc[i][j] = 0.f;

    float4 pa[2], pb[BL];
    // prologue: load K-tile 0 into registers
#pragma unroll
    for (int l = 0; l < 2; l++) {
        int idx = l * 256 + tid;
        int r = idx >> 2, c4 = (idx & 3) * 4;
        int gr = row0 + r;
        pa[l] = (gr < NN) ? *(const float4*)&Ab[(size_t)gr * 128 + c4]
                          : make_float4(0.f, 0.f, 0.f, 0.f);
    }
#pragma unroll
    for (int l = 0; l < BL; l++) {
        int idx = l * 256 + tid;
        int r = idx / (BN / 4), c4 = (idx % (BN / 4)) * 4;
        pb[l] = *(const float4*)&B[(size_t)r * BN + c4];
    }
    // store stage 0
#pragma unroll
    for (int l = 0; l < 2; l++) {
        int idx = l * 256 + tid;
        int r = idx >> 2, c4 = (idx & 3) * 4;
        As[0][c4 + 0][r] = pa[l].x;
        As[0][c4 + 1][r] = pa[l].y;
        As[0][c4 + 2][r] = pa[l].z;
        As[0][c4 + 3][r] = pa[l].w;
    }
#pragma unroll
    for (int l = 0; l < BL; l++) {
        int idx = l * 256 + tid;
        int r = idx / (BN / 4), c4 = (idx % (BN / 4)) * 4;
        *(float4*)&Bs[0][r][c4] = pb[l];
    }
    __syncthreads();

#pragma unroll 1
    for (int t = 0; t < 8; t++) {
        const int cur = t & 1;
        // prefetch next K-tile into registers (overlaps with compute below)
        if (t < 7) {
            const int k0 = (t + 1) * BK;
#pragma unroll
            for (int l = 0; l < 2; l++) {
                int idx = l * 256 + tid;
                int r = idx >> 2, c4 = (idx & 3) * 4;
                int gr = row0 + r;
                pa[l] = (gr < NN)
                            ? *(const float4*)&Ab[(size_t)gr * 128 + k0 + c4]
                            : make_float4(0.f, 0.f, 0.f, 0.f);
            }
#pragma unroll
            for (int l = 0; l < BL; l++) {
                int idx = l * 256 + tid;
                int r = idx / (BN / 4), c4 = (idx % (BN / 4)) * 4;
                pb[l] = *(const float4*)&B[(size_t)(k0 + r) * BN + c4];
            }
        }
        // compute on current stage
#pragma unroll
        for (int k = 0; k < BK; k++) {
            float a[TM], bb[TN];
#pragma unroll
            for (int i4 = 0; i4 < TM; i4 += 4)
                *(float4*)&a[i4] = *(const float4*)&As[cur][k][ty * TM + i4];
#pragma unroll
            for (int j4 = 0; j4 < TN; j4 += 4)
                *(float4*)&bb[j4] = *(const float4*)&Bs[cur][k][tx * TN + j4];
#pragma unroll
            for (int i = 0; i < TM; i++)
#pragma unroll
                for (int j = 0; j < TN; j++) acc[i][j] += a[i] * bb[j];
        }
        // store prefetched tile into the other stage
        if (t < 7) {
            const int nxt = cur ^ 1;
#pragma unroll
            for (int l = 0; l < 2; l++) {
                int idx = l * 256 + tid;
                int r = idx >> 2, c4 = (idx & 3) * 4;
                As[nxt][c4 + 0][r] = pa[l].x;
                As[nxt][c4 + 1][r] = pa[l].y;
                As[nxt][c4 + 2][r] = pa[l].z;
                As[nxt][c4 + 3][r] = pa[l].w;
            }
#pragma unroll
            for (int l = 0; l < BL; l++) {
                int idx = l * 256 + tid;
                int r = idx / (BN / 4), c4 = (idx % (BN / 4)) * 4;
                *(float4*)&Bs[nxt][r][c4] = pb[l];
            }
        }
        __syncthreads();
    }

#pragma unroll
    for (int i = 0; i < TM; i++) {
        int gr = row0 + ty * TM + i;
        if (gr < NN) {
#pragma unroll
            for (int j4 = 0; j4 < TN; j4 += 4)
                *(float4*)&g_xl[(size_t)gr * BN + tx * TN + j4] =
                    *(const float4*)&acc[i][j4];
        }
    }
}

// ---------------- per-(node,head) attention dot products --------------------
__global__ void att_kernel(const float* __restrict__ asrc,
                           const float* __restrict__ adst, int Hh) {
    int g = (blockIdx.x * blockDim.x + threadIdx.x) >> 5;
    int lane = threadIdx.x & 31;
    if (g >= NN * Hh) return;
    int node = g / Hh;
    int h = g - node * Hh;
    const float* row = g_xl + (size_t)node * Hh * 64 + h * 64;
    float v0 = row[lane], v1 = row[lane + 32];
    float vs = v0 * asrc[h * 64 + lane] + v1 * asrc[h * 64 + lane + 32];
    float vd = v0 * adst[h * 64 + lane] + v1 * adst[h * 64 + lane + 32];
#pragma unroll
    for (int o = 16; o; o >>= 1) {
        vs += __shfl_down_sync(0xFFFFFFFFu, vs, o);
        vd += __shfl_down_sync(0xFFFFFFFFu, vd, o);
    }
    if (lane == 0) {
        g_s[node * Hh + h] = vs;
        g_d[node * Hh + h] = vd;
    }
}

// ---------------- CSR build (once per launch) -------------------------------
__global__ void zero_cnt_kernel() {
    int i = blockIdx.x * blockDim.x + threadIdx.x;
    if (i < NN) g_cnt[i] = 0;
}

__global__ void count_kernel(const int* __restrict__ ei) {
    int e = blockIdx.x * blockDim.x + threadIdx.x;
    if (e >= ET) return;
    int d = (e < EE) ? ei[EE + e] : e - EE;
    atomicAdd(&g_cnt[d], 1);
}

// exclusive scan of g_cnt into g_rowptr; leaves fill cursor in g_cnt.
__global__ void scan_kernel() {
    __shared__ int ps[1024];
    const int t = threadIdx.x;
    const int CH = (NN + 1023) / 1024;
    int base = t * CH;
    int sum = 0;
    for (int i = 0; i < CH; i++) {
        int idx = base + i;
        if (idx < NN) sum += g_cnt[idx];
    }
    ps[t] = sum;
    __syncthreads();
    for (int off = 1; off < 1024; off <<= 1) {
        int v = (t >= off) ? ps[t - off] : 0;
        __syncthreads();
        ps[t] += v;
        __syncthreads();
    }
    int run = (t == 0) ? 0 : ps[t - 1];
    for (int i = 0; i < CH; i++) {
        int idx = base + i;
        if (idx < NN) {
            g_rowptr[idx] = run;
            int c = g_cnt[idx];
            g_cnt[idx] = run;   // fill cursor
            run += c;
        }
    }
    if (t == 1023) g_rowptr[NN] = run;
}

__global__ void fill_kernel(const int* __restrict__ ei) {
    int e = blockIdx.x * blockDim.x + threadIdx.x;
    if (e >= ET) return;
    int s, d;
    if (e < EE) { s = ei[e]; d = ei[EE + e]; }
    else        { s = d = e - EE; }
    int pos = atomicAdd(&g_cnt[d], 1);
    g_src[pos] = s;
}

// ---------------- fused softmax + aggregate + bias + elu --------------------
// One warp per dst node. M = Hh*64 (128 or 64).
template <int M>
__global__ void __launch_bounds__(256) agg_kernel(const float* __restrict__ bias,
                                                  float* __restrict__ outp,
                                                  int do_elu, int dst_is_gh) {
    constexpr int Hh = M / 64;
    constexpr int VEC = M / 32;
    __shared__ float sh_ex[8][Hh][32];
    __shared__ int   sh_s[8][32];
    const int w = threadIdx.x >> 5, lane = threadIdx.x & 31;
    const int node = blockIdx.x * 8 + w;
    if (node >= NN) return;
    const int start = g_rowptr[node], end = g_rowptr[node + 1];
    const int h = (Hh == 2) ? (lane >> 4) : 0;

    const float d0 = g_d[node * Hh + 0];
    const float d1 = (Hh == 2) ? g_d[node * Hh + 1] : 0.f;

    float m0 = -3.4e38f, m1 = -3.4e38f;
    for (int e = start + lane; e < end; e += 32) {
        int s = g_src[e];
        float v0 = g_s[s * Hh + 0] + d0;
        v0 = v0 > 0.f ? v0 : 0.2f * v0;
        m0 = fmaxf(m0, v0);
        if (Hh == 2) {
            float v1 = g_s[s * Hh + 1] + d1;
            v1 = v1 > 0.f ? v1 : 0.2f * v1;
            m1 = fmaxf(m1, v1);
        }
    }
#pragma unroll
    for (int o = 16; o; o >>= 1) {
        m0 = fmaxf(m0, __shfl_xor_sync(0xFFFFFFFFu, m0, o));
        if (Hh == 2) m1 = fmaxf(m1, __shfl_xor_sync(0xFFFFFFFFu, m1, o));
    }

    float acc[VEC];
#pragma unroll
    for (int k = 0; k < VEC; k++) acc[k] = 0.f;
    float denom = 0.f;

    for (int c0 = start; c0 < end; c0 += 32) {
        int n = min(32, end - c0);
        if (lane < n) {
            int s = g_src[c0 + lane];
            sh_s[w][lane] = s;
            float v0 = g_s[s * Hh + 0] + d0;
            v0 = v0 > 0.f ? v0 : 0.2f * v0;
            sh_ex[w][0][lane] = __expf(v0 - m0);
            if (Hh == 2) {
                float v1 = g_s[s * Hh + 1] + d1;
                v1 = v1 > 0.f ? v1 : 0.2f * v1;
                sh_ex[w][1][lane] = __expf(v1 - m1);
            }
        }
        __syncwarp();
#pragma unroll 4
        for (int j = 0; j < n; j++) {
            int s = sh_s[w][j];
            float ex = sh_ex[w][h][j];
            denom += ex;
            const float* xr = &g_xl[(size_t)s * M + lane * VEC];
            if (VEC == 4) {
                float4 xv = *(const float4*)xr;
                acc[0] += ex * xv.x;
                acc[1] += ex * xv.y;
                acc[2] += ex * xv.z;
                acc[3] += ex * xv.w;
            } else {
                float2 xv = *(const float2*)xr;
                acc[0] += ex * xv.x;
                acc[1] += ex * xv.y;
            }
        }
        __syncwarp();
    }

    float inv = 1.f / denom;
    float* dst = dst_is_gh ? (float*)g_h : outp;
    int col = lane * VEC;
#pragma unroll
    for (int k = 0; k < VEC; k++) {
        float v = acc[k] * inv + bias[col + k];
        if (do_elu) v = v > 0.f ? v : expm1f(v);
        dst[(size_t)node * M + col + k] = v;
    }
}

// ---------------- host-side driver (kernel launches ONLY) -------------------
static void run_layer(const float* in, const float* W, const float* asrc,
                      const float* adst, const float* bias, float* outp,
                      int Hh, int do_elu, int src_is_gh, int dst_is_gh) {
    const int M = Hh * 64;
    if (M == 128)
        gemm_kernel<128><<<(NN + 127) / 128, 256>>>(in, W, src_is_gh);
    else
        gemm_kernel<64><<<(NN + 127) / 128, 256>>>(in, W, src_is_gh);

    int warps = NN * Hh;
    att_kernel<<<(warps * 32 + 255) / 256, 256>>>(asrc, adst, Hh);

    if (M == 128)
        agg_kernel<128><<<(NN + 7) / 8, 256>>>(bias, outp, do_elu, dst_is_gh);
    else
        agg_kernel<64><<<(NN + 7) / 8, 256>>>(bias, outp, do_elu, dst_is_gh);
}

extern "C" void kernel_launch(void* const* d_in, const int* in_sizes, int n_in,
                              void* d_out, int out_size) {
    const float* x   = (const float*)d_in[0];
    const int*   ei  = (const int*)d_in[1];   // int64 in reference -> int32 here
    const float* W0  = (const float*)d_in[2];
    const float* as0 = (const float*)d_in[3];
    const float* ad0 = (const float*)d_in[4];
    const float* b0  = (const float*)d_in[5];
    const float* W1  = (const float*)d_in[6];
    const float* as1 = (const float*)d_in[7];
    const float* ad1 = (const float*)d_in[8];
    const float* b1  = (const float*)d_in[9];
    const float* W2  = (const float*)d_in[10];
    const float* as2 = (const float*)d_in[11];
    const float* ad2 = (const float*)d_in[12];
    const float* b2  = (const float*)d_in[13];

    // CSR by dst (edge structure shared by all 3 layers)
    zero_cnt_kernel<<<(NN + 255) / 256, 256>>>();
    count_kernel<<<(ET + 255) / 256, 256>>>(ei);
    scan_kernel<<<1, 1024>>>();
    fill_kernel<<<(ET + 255) / 256, 256>>>(ei);

    run_layer(x, W0, as0, ad0, b0, nullptr,       2, 1, 0, 1);
    run_layer(x, W1, as1, ad1, b1, nullptr,       2, 1, 1, 1);
    run_layer(x, W2, as2, ad2, b2, (float*)d_out, 1, 0, 1, 0);
}

// round 12
// speedup vs baseline: 1.0996x; 1.0996x over previous
#include <cuda_runtime.h>

#define NN 50000
#define EE 800000
#define ET (EE + NN)

// ---------------- scratch (device globals; no allocations allowed) ----------
__device__ float g_xl[NN * 128];     // transformed features [N, M]
__device__ float g_h[NN * 128];      // inter-layer activations
__device__ float g_s[NN * 2];        // alpha_src per (node, head)
__device__ float g_d[NN * 2];        // alpha_dst per (node, head)
__device__ int   g_rowptr[NN + 1];   // CSR row pointers (by dst)
__device__ int   g_cnt[NN];          // degree counts / fill cursors
__device__ int   g_src[ET];          // CSR: src node per incoming edge

// ---------------- GEMM + fused attention dots -------------------------------
// [N,128] @ [128,BN] -> g_xl[N,BN]; epilogue computes g_s/g_d from registers.
// 128xBNx16 tile, 256 threads, 8x(BN/16) per thread (R8-proven config).
template <int BN>
__global__ void __launch_bounds__(256) gemm_kernel(const float* __restrict__ A,
                                                   const float* __restrict__ B,
                                                   const float* __restrict__ asrc,
                                                   const float* __restrict__ adst,
                                                   int src_is_gh) {
    constexpr int BM = 128, BK = 16, TM = 8, TN = BN / 16;
    constexpr int Hh = BN / 64;
    __shared__ float As[BK][BM + 4];
    __shared__ float Bs[BK][BN];
    const float* __restrict__ Ab = src_is_gh ? (const float*)g_h : A;
    const int tid = threadIdx.x;
    const int tx = tid & 15, ty = tid >> 4;
    const int row0 = blockIdx.x * BM;

    float acc[TM][TN];
#pragma unroll
    for (int i = 0; i < TM; i++)
#pragma unroll
        for (int j = 0; j < TN; j++) acc[i][j] = 0.f;

    for (int k0 = 0; k0 < 128; k0 += BK) {
#pragma unroll
        for (int l = 0; l < 2; l++) {
            int idx = l * 256 + tid;
            int r = idx >> 2;
            int c4 = (idx & 3) * 4;
            int gr = row0 + r;
            float4 v = make_float4(0.f, 0.f, 0.f, 0.f);
            if (gr < NN) v = *(const float4*)&Ab[(size_t)gr * 128 + k0 + c4];
            As[c4 + 0][r] = v.x;
            As[c4 + 1][r] = v.y;
            As[c4 + 2][r] = v.z;
            As[c4 + 3][r] = v.w;
        }
#pragma unroll
        for (int l = 0; l < (BK * BN) / (4 * 256); l++) {
            int idx = l * 256 + tid;
            int r = idx / (BN / 4);
            int c4 = (idx % (BN / 4)) * 4;
            *(float4*)&Bs[r][c4] = *(const float4*)&B[(size_t)(k0 + r) * BN + c4];
        }
        __syncthreads();
#pragma unroll
        for (int k = 0; k < BK; k++) {
            float a[TM], bb[TN];
#pragma unroll
            for (int i4 = 0; i4 < TM; i4 += 4)
                *(float4*)&a[i4] = *(const float4*)&As[k][ty * TM + i4];
#pragma unroll
            for (int j4 = 0; j4 < TN; j4 += 4)
                *(float4*)&bb[j4] = *(const float4*)&Bs[k][tx * TN + j4];
#pragma unroll
            for (int i = 0; i < TM; i++)
#pragma unroll
                for (int j = 0; j < TN; j++) acc[i][j] += a[i] * bb[j];
        }
        __syncthreads();
    }

    // store xl tile
#pragma unroll
    for (int i = 0; i < TM; i++) {
        int gr = row0 + ty * TM + i;
        if (gr < NN) {
#pragma unroll
            for (int j4 = 0; j4 < TN; j4 += 4)
                *(float4*)&g_xl[(size_t)gr * BN + tx * TN + j4] =
                    *(const float4*)&acc[i][j4];
        }
    }

    // fused attention dots: this thread's cols lie within one head.
    // BN=128: head = tx/8, reduce over 8 lanes; BN=64: head 0, reduce over 16.
    const int h = (Hh == 2) ? (tx >> 3) : 0;
    const int colbase = tx * TN - h * 64;
    float sa[TN], da[TN];
#pragma unroll
    for (int j = 0; j < TN; j++) {
        sa[j] = asrc[h * 64 + colbase + j];
        da[j] = adst[h * 64 + colbase + j];
    }
    constexpr int RW = (Hh == 2) ? 8 : 16;   // reduction width in lanes
#pragma unroll
    for (int i = 0; i < TM; i++) {
        float vs = 0.f, vd = 0.f;
#pragma unroll
        for (int j = 0; j < TN; j++) {
            vs += acc[i][j] * sa[j];
            vd += acc[i][j] * da[j];
        }
#pragma unroll
        for (int o = RW / 2; o; o >>= 1) {
            vs += __shfl_down_sync(0xFFFFFFFFu, vs, o, RW);
            vd += __shfl_down_sync(0xFFFFFFFFu, vd, o, RW);
        }
        int gr = row0 + ty * TM + i;
        bool writer = (Hh == 2) ? ((tx & 7) == 0) : (tx == 0);
        if (writer && gr < NN) {
            g_s[gr * Hh + h] = vs;
            g_d[gr * Hh + h] = vd;
        }
    }
}

// ---------------- CSR build (once per launch) -------------------------------
__global__ void zero_cnt_kernel() {
    int i = blockIdx.x * blockDim.x + threadIdx.x;
    if (i < NN) g_cnt[i] = 0;
}

__global__ void count_kernel(const int* __restrict__ ei) {
    int e = blockIdx.x * blockDim.x + threadIdx.x;
    if (e >= ET) return;
    int d = (e < EE) ? ei[EE + e] : e - EE;
    atomicAdd(&g_cnt[d], 1);
}

// exclusive scan of g_cnt into g_rowptr; leaves fill cursor in g_cnt.
__global__ void scan_kernel() {
    __shared__ int ps[1024];
    const int t = threadIdx.x;
    const int CH = (NN + 1023) / 1024;
    int base = t * CH;
    int sum = 0;
    for (int i = 0; i < CH; i++) {
        int idx = base + i;
        if (idx < NN) sum += g_cnt[idx];
    }
    ps[t] = sum;
    __syncthreads();
    for (int off = 1; off < 1024; off <<= 1) {
        int v = (t >= off) ? ps[t - off] : 0;
        __syncthreads();
        ps[t] += v;
        __syncthreads();
    }
    int run = (t == 0) ? 0 : ps[t - 1];
    for (int i = 0; i < CH; i++) {
        int idx = base + i;
        if (idx < NN) {
            g_rowptr[idx] = run;
            int c = g_cnt[idx];
            g_cnt[idx] = run;   // fill cursor
            run += c;
        }
    }
    if (t == 1023) g_rowptr[NN] = run;
}

__global__ void fill_kernel(const int* __restrict__ ei) {
    int e = blockIdx.x * blockDim.x + threadIdx.x;
    if (e >= ET) return;
    int s, d;
    if (e < EE) { s = ei[e]; d = ei[EE + e]; }
    else        { s = d = e - EE; }
    int pos = atomicAdd(&g_cnt[d], 1);
    g_src[pos] = s;
}

// ---------------- fused softmax + aggregate + bias + elu --------------------
// One warp per dst node. M = Hh*64 (128 or 64).
template <int M>
__global__ void __launch_bounds__(256) agg_kernel(const float* __restrict__ bias,
                                                  float* __restrict__ outp,
                                                  int do_elu, int dst_is_gh) {
    constexpr int Hh = M / 64;
    constexpr int VEC = M / 32;
    __shared__ float sh_ex[8][Hh][32];
    __shared__ int   sh_s[8][32];
    const int w = threadIdx.x >> 5, lane = threadIdx.x & 31;
    const int node = blockIdx.x * 8 + w;
    if (node >= NN) return;
    const int start = g_rowptr[node], end = g_rowptr[node + 1];
    const int h = (Hh == 2) ? (lane >> 4) : 0;

    const float d0 = g_d[node * Hh + 0];
    const float d1 = (Hh == 2) ? g_d[node * Hh + 1] : 0.f;

    float m0 = -3.4e38f, m1 = -3.4e38f;
    for (int e = start + lane; e < end; e += 32) {
        int s = g_src[e];
        float v0 = g_s[s * Hh + 0] + d0;
        v0 = v0 > 0.f ? v0 : 0.2f * v0;
        m0 = fmaxf(m0, v0);
        if (Hh == 2) {
            float v1 = g_s[s * Hh + 1] + d1;
            v1 = v1 > 0.f ? v1 : 0.2f * v1;
            m1 = fmaxf(m1, v1);
        }
    }
#pragma unroll
    for (int o = 16; o; o >>= 1) {
        m0 = fmaxf(m0, __shfl_xor_sync(0xFFFFFFFFu, m0, o));
        if (Hh == 2) m1 = fmaxf(m1, __shfl_xor_sync(0xFFFFFFFFu, m1, o));
    }

    float acc[VEC];
#pragma unroll
    for (int k = 0; k < VEC; k++) acc[k] = 0.f;
    float denom = 0.f;

    for (int c0 = start; c0 < end; c0 += 32) {
        int n = min(32, end - c0);
        if (lane < n) {
            int s = g_src[c0 + lane];
            sh_s[w][lane] = s;
            float v0 = g_s[s * Hh + 0] + d0;
            v0 = v0 > 0.f ? v0 : 0.2f * v0;
            sh_ex[w][0][lane] = __expf(v0 - m0);
            if (Hh == 2) {
                float v1 = g_s[s * Hh + 1] + d1;
                v1 = v1 > 0.f ? v1 : 0.2f * v1;
                sh_ex[w][1][lane] = __expf(v1 - m1);
            }
        }
        __syncwarp();
#pragma unroll 4
        for (int j = 0; j < n; j++) {
            int s = sh_s[w][j];
            float ex = sh_ex[w][h][j];
            denom += ex;
            const float* xr = &g_xl[(size_t)s * M + lane * VEC];
            if (VEC == 4) {
                float4 xv = *(const float4*)xr;
                acc[0] += ex * xv.x;
                acc[1] += ex * xv.y;
                acc[2] += ex * xv.z;
                acc[3] += ex * xv.w;
            } else {
                float2 xv = *(const float2*)xr;
                acc[0] += ex * xv.x;
                acc[1] += ex * xv.y;
            }
        }
        __syncwarp();
    }

    float inv = 1.f / denom;
    float* dst = dst_is_gh ? (float*)g_h : outp;
    int col = lane * VEC;
#pragma unroll
    for (int k = 0; k < VEC; k++) {
        float v = acc[k] * inv + bias[col + k];
        if (do_elu) v = v > 0.f ? v : expm1f(v);
        dst[(size_t)node * M + col + k] = v;
    }
}

// ---------------- host-side driver (kernel launches ONLY) -------------------
static void run_layer(const float* in, const float* W, const float* asrc,
                      const float* adst, const float* bias, float* outp,
                      int Hh, int do_elu, int src_is_gh, int dst_is_gh) {
    const int M = Hh * 64;
    if (M == 128)
        gemm_kernel<128><<<(NN + 127) / 128, 256>>>(in, W, asrc, adst, src_is_gh);
    else
        gemm_kernel<64><<<(NN + 127) / 128, 256>>>(in, W, asrc, adst, src_is_gh);

    if (M == 128)
        agg_kernel<128><<<(NN + 7) / 8, 256>>>(bias, outp, do_elu, dst_is_gh);
    else
        agg_kernel<64><<<(NN + 7) / 8, 256>>>(bias, outp, do_elu, dst_is_gh);
}

extern "C" void kernel_launch(void* const* d_in, const int* in_sizes, int n_in,
                              void* d_out, int out_size) {
    const float* x   = (const float*)d_in[0];
    const int*   ei  = (const int*)d_in[1];   // int64 in reference -> int32 here
    const float* W0  = (const float*)d_in[2];
    const float* as0 = (const float*)d_in[3];
    const float* ad0 = (const float*)d_in[4];
    const float* b0  = (const float*)d_in[5];
    const float* W1  = (const float*)d_in[6];
    const float* as1 = (const float*)d_in[7];
    const float* ad1 = (const float*)d_in[8];
    const float* b1  = (const float*)d_in[9];
    const float* W2  = (const float*)d_in[10];
    const float* as2 = (const float*)d_in[11];
    const float* ad2 = (const float*)d_in[12];
    const float* b2  = (const float*)d_in[13];

    // CSR by dst (edge structure shared by all 3 layers)
    zero_cnt_kernel<<<(NN + 255) / 256, 256>>>();
    count_kernel<<<(ET + 255) / 256, 256>>>(ei);
    scan_kernel<<<1, 1024>>>();
    fill_kernel<<<(ET + 255) / 256, 256>>>(ei);

    run_layer(x, W0, as0, ad0, b0, nullptr,       2, 1, 0, 1);
    run_layer(x, W1, as1, ad1, b1, nullptr,       2, 1, 1, 1);
    run_layer(x, W2, as2, ad2, b2, (float*)d_out, 1, 0, 1, 0);
}

// round 13
// speedup vs baseline: 1.1439x; 1.0403x over previous
#include <cuda_runtime.h>
#include <cstdint>

#define NN 50000
#define EE 800000
#define ET (EE + NN)

// ---------------- scratch (device globals; no allocations allowed) ----------
__device__ float g_xl[NN * 128];     // transformed features [N, M]
__device__ float g_h[NN * 128];      // inter-layer activations
__device__ float g_s[NN * 2];        // alpha_src per (node, head)
__device__ float g_d[NN * 2];        // alpha_dst per (node, head)
__device__ int   g_rowptr[NN + 1];   // CSR row pointers (by dst)
__device__ int   g_cnt[NN];          // degree counts / fill cursors
__device__ int   g_src[ET];          // CSR: src node per incoming edge

// ---------------- tf32 helpers ----------------------------------------------
__device__ __forceinline__ uint32_t to_tf32(float f) {
    uint32_t r;
    asm("cvt.rna.tf32.f32 %0, %1;" : "=r"(r) : "f"(f));
    return r;
}
__device__ __forceinline__ void mma_tf32(float* c, uint32_t a0, uint32_t a1,
                                         uint32_t a2, uint32_t a3,
                                         uint32_t b0, uint32_t b1) {
    asm volatile(
        "mma.sync.aligned.m16n8k8.row.col.f32.tf32.tf32.f32 "
        "{%0,%1,%2,%3}, {%4,%5,%6,%7}, {%8,%9}, {%0,%1,%2,%3};"
        : "+f"(c[0]), "+f"(c[1]), "+f"(c[2]), "+f"(c[3])
        : "r"(a0), "r"(a1), "r"(a2), "r"(a3), "r"(b0), "r"(b1));
}

// ---------------- GEMM: [N,128] @ [128,BN] -> g_xl[N,BN] (tf32 MMA) ---------
// 256 threads = 8 warps; warp w owns rows 16w..16w+15, all BN cols.
template <int BN>
__global__ void __launch_bounds__(256) gemm_kernel(const float* __restrict__ A,
                                                   const float* __restrict__ B,
                                                   int src_is_gh) {
    constexpr int BM = 128, BK = 32;
    constexpr int NT = BN / 8;            // n-tiles per warp
    constexpr int BL = (BK * BN) / (4 * 256);  // B float4 loads per thread
    __shared__ uint32_t As[BM][36];       // tf32 bits, stride 36 (16B-aligned, cf-free frags)
    __shared__ uint32_t Bs[BK][BN + 4];   // tf32 bits, stride BN+4
    const float* __restrict__ Ab = src_is_gh ? (const float*)g_h : A;
    const int tid = threadIdx.x;
    const int lane = tid & 31, w = tid >> 5;
    const int row0 = blockIdx.x * BM;

    float c[NT][4];
#pragma unroll
    for (int j = 0; j < NT; j++)
#pragma unroll
        for (int q = 0; q < 4; q++) c[j][q] = 0.f;

    const int qr = lane >> 2, qc = lane & 3;   // quad row / quad col

    for (int t = 0; t < 4; t++) {
        const int k0 = t * BK;
        // A tile: 128x32 floats = 1024 float4, 4 per thread
#pragma unroll
        for (int l = 0; l < 4; l++) {
            int idx = l * 256 + tid;
            int r = idx >> 3, c4 = (idx & 7) * 4;
            int gr = row0 + r;
            float4 v = make_float4(0.f, 0.f, 0.f, 0.f);
            if (gr < NN) v = *(const float4*)&Ab[(size_t)gr * 128 + k0 + c4];
            As[r][c4 + 0] = to_tf32(v.x);
            As[r][c4 + 1] = to_tf32(v.y);
            As[r][c4 + 2] = to_tf32(v.z);
            As[r][c4 + 3] = to_tf32(v.w);
        }
        // B tile: 32xBN floats
#pragma unroll
        for (int l = 0; l < BL; l++) {
            int idx = l * 256 + tid;
            int r = idx / (BN / 4), c4 = (idx % (BN / 4)) * 4;
            float4 v = *(const float4*)&B[(size_t)(k0 + r) * BN + c4];
            Bs[r][c4 + 0] = to_tf32(v.x);
            Bs[r][c4 + 1] = to_tf32(v.y);
            Bs[r][c4 + 2] = to_tf32(v.z);
            Bs[r][c4 + 3] = to_tf32(v.w);
        }
        __syncthreads();
#pragma unroll
        for (int ks = 0; ks < 4; ks++) {
            const int k = ks * 8;
            uint32_t a0 = As[16 * w + qr][k + qc];
            uint32_t a1 = As[16 * w + qr + 8][k + qc];
            uint32_t a2 = As[16 * w + qr][k + qc + 4];
            uint32_t a3 = As[16 * w + qr + 8][k + qc + 4];
#pragma unroll
            for (int j = 0; j < NT; j++) {
                uint32_t b0 = Bs[k + qc][8 * j + qr];
                uint32_t b1 = Bs[k + 4 + qc][8 * j + qr];
                mma_tf32(c[j], a0, a1, a2, a3, b0, b1);
            }
        }
        __syncthreads();
    }

    // store: c[j] covers rows (16w+qr, +8), cols 8j+2*qc+{0,1}
    const int gr0 = row0 + 16 * w + qr;
    const int gr1 = gr0 + 8;
#pragma unroll
    for (int j = 0; j < NT; j++) {
        int col = 8 * j + 2 * qc;
        if (gr0 < NN)
            *(float2*)&g_xl[(size_t)gr0 * BN + col] = make_float2(c[j][0], c[j][1]);
        if (gr1 < NN)
            *(float2*)&g_xl[(size_t)gr1 * BN + col] = make_float2(c[j][2], c[j][3]);
    }
}

// ---------------- per-(node,head) attention dot products --------------------
__global__ void att_kernel(const float* __restrict__ asrc,
                           const float* __restrict__ adst, int Hh) {
    int g = (blockIdx.x * blockDim.x + threadIdx.x) >> 5;
    int lane = threadIdx.x & 31;
    if (g >= NN * Hh) return;
    int node = g / Hh;
    int h = g - node * Hh;
    const float* row = g_xl + (size_t)node * Hh * 64 + h * 64;
    float v0 = row[lane], v1 = row[lane + 32];
    float vs = v0 * asrc[h * 64 + lane] + v1 * asrc[h * 64 + lane + 32];
    float vd = v0 * adst[h * 64 + lane] + v1 * adst[h * 64 + lane + 32];
#pragma unroll
    for (int o = 16; o; o >>= 1) {
        vs += __shfl_down_sync(0xFFFFFFFFu, vs, o);
        vd += __shfl_down_sync(0xFFFFFFFFu, vd, o);
    }
    if (lane == 0) {
        g_s[node * Hh + h] = vs;
        g_d[node * Hh + h] = vd;
    }
}

// ---------------- CSR build (once per launch) -------------------------------
__global__ void zero_cnt_kernel() {
    int i = blockIdx.x * blockDim.x + threadIdx.x;
    if (i < NN) g_cnt[i] = 0;
}

__global__ void count_kernel(const int* __restrict__ ei) {
    int e = blockIdx.x * blockDim.x + threadIdx.x;
    if (e >= ET) return;
    int d = (e < EE) ? ei[EE + e] : e - EE;
    atomicAdd(&g_cnt[d], 1);
}

__global__ void scan_kernel() {
    __shared__ int ps[1024];
    const int t = threadIdx.x;
    const int CH = (NN + 1023) / 1024;
    int base = t * CH;
    int sum = 0;
    for (int i = 0; i < CH; i++) {
        int idx = base + i;
        if (idx < NN) sum += g_cnt[idx];
    }
    ps[t] = sum;
    __syncthreads();
    for (int off = 1; off < 1024; off <<= 1) {
        int v = (t >= off) ? ps[t - off] : 0;
        __syncthreads();
        ps[t] += v;
        __syncthreads();
    }
    int run = (t == 0) ? 0 : ps[t - 1];
    for (int i = 0; i < CH; i++) {
        int idx = base + i;
        if (idx < NN) {
            g_rowptr[idx] = run;
            int c = g_cnt[idx];
            g_cnt[idx] = run;   // fill cursor
            run += c;
        }
    }
    if (t == 1023) g_rowptr[NN] = run;
}

__global__ void fill_kernel(const int* __restrict__ ei) {
    int e = blockIdx.x * blockDim.x + threadIdx.x;
    if (e >= ET) return;
    int s, d;
    if (e < EE) { s = ei[e]; d = ei[EE + e]; }
    else        { s = d = e - EE; }
    int pos = atomicAdd(&g_cnt[d], 1);
    g_src[pos] = s;
}

// ---------------- fused softmax + aggregate + bias + elu --------------------
template <int M>
__global__ void __launch_bounds__(256) agg_kernel(const float* __restrict__ bias,
                                                  float* __restrict__ outp,
                                                  int do_elu, int dst_is_gh) {
    constexpr int Hh = M / 64;
    constexpr int VEC = M / 32;
    __shared__ float sh_ex[8][Hh][32];
    __shared__ int   sh_s[8][32];
    const int w = threadIdx.x >> 5, lane = threadIdx.x & 31;
    const int node = blockIdx.x * 8 + w;
    if (node >= NN) return;
    const int start = g_rowptr[node], end = g_rowptr[node + 1];
    const int h = (Hh == 2) ? (lane >> 4) : 0;

    const float d0 = g_d[node * Hh + 0];
    const float d1 = (Hh == 2) ? g_d[node * Hh + 1] : 0.f;

    float m0 = -3.4e38f, m1 = -3.4e38f;
    for (int e = start + lane; e < end; e += 32) {
        int s = g_src[e];
        float v0 = g_s[s * Hh + 0] + d0;
        v0 = v0 > 0.f ? v0 : 0.2f * v0;
        m0 = fmaxf(m0, v0);
        if (Hh == 2) {
            float v1 = g_s[s * Hh + 1] + d1;
            v1 = v1 > 0.f ? v1 : 0.2f * v1;
            m1 = fmaxf(m1, v1);
        }
    }
#pragma unroll
    for (int o = 16; o; o >>= 1) {
        m0 = fmaxf(m0, __shfl_xor_sync(0xFFFFFFFFu, m0, o));
        if (Hh == 2) m1 = fmaxf(m1, __shfl_xor_sync(0xFFFFFFFFu, m1, o));
    }

    float acc[VEC];
#pragma unroll
    for (int k = 0; k < VEC; k++) acc[k] = 0.f;
    float denom = 0.f;

    for (int c0 = start; c0 < end; c0 += 32) {
        int n = min(32, end - c0);
        if (lane < n) {
            int s = g_src[c0 + lane];
            sh_s[w][lane] = s;
            float v0 = g_s[s * Hh + 0] + d0;
            v0 = v0 > 0.f ? v0 : 0.2f * v0;
            sh_ex[w][0][lane] = __expf(v0 - m0);
            if (Hh == 2) {
                float v1 = g_s[s * Hh + 1] + d1;
                v1 = v1 > 0.f ? v1 : 0.2f * v1;
                sh_ex[w][1][lane] = __expf(v1 - m1);
            }
        }
        __syncwarp();
#pragma unroll 4
        for (int j = 0; j < n; j++) {
            int s = sh_s[w][j];
            float ex = sh_ex[w][h][j];
            denom += ex;
            const float* xr = &g_xl[(size_t)s * M + lane * VEC];
            if (VEC == 4) {
                float4 xv = *(const float4*)xr;
                acc[0] += ex * xv.x;
                acc[1] += ex * xv.y;
                acc[2] += ex * xv.z;
                acc[3] += ex * xv.w;
            } else {
                float2 xv = *(const float2*)xr;
                acc[0] += ex * xv.x;
                acc[1] += ex * xv.y;
            }
        }
        __syncwarp();
    }

    float inv = 1.f / denom;
    float* dst = dst_is_gh ? (float*)g_h : outp;
    int col = lane * VEC;
#pragma unroll
    for (int k = 0; k < VEC; k++) {
        float v = acc[k] * inv + bias[col + k];
        if (do_elu) v = v > 0.f ? v : expm1f(v);
        dst[(size_t)node * M + col + k] = v;
    }
}

// ---------------- host-side driver (kernel launches ONLY) -------------------
static void run_layer(const float* in, const float* W, const float* asrc,
                      const float* adst, const float* bias, float* outp,
                      int Hh, int do_elu, int src_is_gh, int dst_is_gh) {
    const int M = Hh * 64;
    if (M == 128)
        gemm_kernel<128><<<(NN + 127) / 128, 256>>>(in, W, src_is_gh);
    else
        gemm_kernel<64><<<(NN + 127) / 128, 256>>>(in, W, src_is_gh);

    int warps = NN * Hh;
    att_kernel<<<(warps * 32 + 255) / 256, 256>>>(asrc, adst, Hh);

    if (M == 128)
        agg_kernel<128><<<(NN + 7) / 8, 256>>>(bias, outp, do_elu, dst_is_gh);
    else
        agg_kernel<64><<<(NN + 7) / 8, 256>>>(bias, outp, do_elu, dst_is_gh);
}

extern "C" void kernel_launch(void* const* d_in, const int* in_sizes, int n_in,
                              void* d_out, int out_size) {
    const float* x   = (const float*)d_in[0];
    const int*   ei  = (const int*)d_in[1];   // int64 in reference -> int32 here
    const float* W0  = (const float*)d_in[2];
    const float* as0 = (const float*)d_in[3];
    const float* ad0 = (const float*)d_in[4];
    const float* b0  = (const float*)d_in[5];
    const float* W1  = (const float*)d_in[6];
    const float* as1 = (const float*)d_in[7];
    const float* ad1 = (const float*)d_in[8];
    const float* b1  = (const float*)d_in[9];
    const float* W2  = (const float*)d_in[10];
    const float* as2 = (const float*)d_in[11];
    const float* ad2 = (const float*)d_in[12];
    const float* b2  = (const float*)d_in[13];

    // CSR by dst (edge structure shared by all 3 layers)
    zero_cnt_kernel<<<(NN + 255) / 256, 256>>>();
    count_kernel<<<(ET + 255) / 256, 256>>>(ei);
    scan_kernel<<<1, 1024>>>();
    fill_kernel<<<(ET + 255) / 256, 256>>>(ei);

    run_layer(x, W0, as0, ad0, b0, nullptr,       2, 1, 0, 1);
    run_layer(x, W1, as1, ad1, b1, nullptr,       2, 1, 1, 1);
    run_layer(x, W2, as2, ad2, b2, (float*)d_out, 1, 0, 1, 0);
}